// round 6
// baseline (speedup 1.0000x reference)
#include <cuda_runtime.h>
#include <cstdint>

#define HORIZON 30
#define INDIM   384
#define BMAX    65536

typedef unsigned long long ull;

// gi_base scratch: [B, 768] fp32 (192 MB) static device scratch.
__device__ float g_gi[(size_t)BMAX * 768];

__device__ __forceinline__ ull pack2(float lo, float hi) {
    ull r; asm("mov.b64 %0, {%1, %2};" : "=l"(r) : "f"(lo), "f"(hi)); return r;
}
__device__ __forceinline__ void ffma2(ull& d, ull a, ull b) {
    asm("fma.rn.f32x2 %0, %1, %2, %0;" : "+l"(d) : "l"(a), "l"(b));
}
__device__ __forceinline__ void unpack2(ull v, float& lo, float& hi) {
    asm("mov.b64 {%0, %1}, %2;" : "=f"(lo), "=f"(hi) : "l"(v));
}
__device__ __forceinline__ float sigf(float x) {
    return __fdividef(1.f, 1.f + __expf(-x));
}
__device__ __forceinline__ float tanh_fast(float x) {
    float t = __expf(2.f * x);
    return 1.f - __fdividef(2.f, t + 1.f);
}
__device__ __forceinline__ void cpa16(uint32_t s, const void* g) {
    asm volatile("cp.async.cg.shared.global [%0], [%1], 16;" :: "r"(s), "l"(g));
}
#define CPA_COMMIT() asm volatile("cp.async.commit_group;")
#define CPA_WAIT1()  asm volatile("cp.async.wait_group 1;")
#define CPA_WAIT0()  asm volatile("cp.async.wait_group 0;")

// ---------------- shared memory layout (floats) ----------------
#define HT_STRIDE 68
#define HT_SIZE   (256 * HT_STRIDE)          // 17408
#define OFF_HT    0                           // 2 ping-pong buffers
#define OFF_W     (2 * HT_SIZE)              // 34816
#define W_ROWPAD  20                          // 16 k + 4 pad
#define WARP_WBUF (24 * W_ROWPAD)            // 480 floats: 24 rows x 16 k (one chunk)
#define W_REGION  (16 * 2 * WARP_WBUF)       // 15360 floats (16 warps x 2 buffers)
#define OFF_WMUX  (OFF_W + W_REGION)         // 50176
#define OFF_WMUY  (OFF_WMUX + 768)
#define OFF_BHH   (OFF_WMUY + 768)
#define OFF_W5    (OFF_BHH + 768)
#define OFF_MUX   (OFF_W5 + 1280)
#define OFF_MUY   (OFF_MUX + 64)
#define SMEM_FLOATS (OFF_MUY + 64)           // 53888 floats = 215552 B

#define NTHR 512

// Per-warp private W staging: warp owns hidden slice j in [jb*128 + warp*8, +8)
// for all 3 gates -> 24 Whh rows. Chunk c = jb*16 + kc covers k in [kc*16, +16).
// Buffer row order: r = g*8 + jj. Only this warp ever reads this region.
__device__ __forceinline__ void issue_chunk_w(uint32_t s_w_u32, const float* __restrict__ Whh,
                                              int c, int warp, int lane) {
    const int jb = (c >> 4) & 1;
    const int kc = c & 15;
    const uint32_t sbuf = s_w_u32 + (uint32_t)((warp * 2 + (c & 1)) * WARP_WBUF * 4);
    #pragma unroll
    for (int o = 0; o < 3; ++o) {
        int t = o * 32 + lane;            // 0..95 tasks: 24 rows x 4 quads
        int r = t >> 2, q = t & 3;
        int g = r >> 3, jj = r & 7;
        const float* gp = Whh + (size_t)(g * 256 + jb * 128 + warp * 8 + jj) * 256
                              + kc * 16 + q * 4;
        cpa16(sbuf + (uint32_t)((r * W_ROWPAD + q * 4) * 4), gp);
    }
}

__global__ void __launch_bounds__(NTHR, 1)
gru_decoder_kernel(const float* __restrict__ zh,  const float* __restrict__ Wh0,
                   const float* __restrict__ bh0, const float* __restrict__ Wih,
                   const float* __restrict__ bih, const float* __restrict__ Whh,
                   const float* __restrict__ bhhg,const float* __restrict__ Wmu,
                   const float* __restrict__ bmu, const float* __restrict__ Wcov,
                   const float* __restrict__ bcov,float* __restrict__ out, int B)
{
    extern __shared__ float sm[];
    float* s_w    = sm + OFF_W;
    float* s_wmux = sm + OFF_WMUX;
    float* s_wmuy = sm + OFF_WMUY;
    float* s_bhh  = sm + OFF_BHH;
    float* s_w5   = sm + OFF_W5;
    float* s_mux  = sm + OFF_MUX;
    float* s_muy  = sm + OFF_MUY;

    const int tid  = threadIdx.x;
    const int warp = tid >> 5, lane = tid & 31;
    const int m0   = (lane & 7) * 8;        // 8 batch rows (4 f32x2 pairs)
    const int jj0  = (lane >> 3) * 2;       // 2 adjacent j within warp's 8-j slice
    const int b0   = blockIdx.x * 64;

    const uint32_t s_w_u32 = (uint32_t)__cvta_generic_to_shared(s_w);

    // ---- one-time small-weight staging ----
    for (int i = tid; i < 768; i += NTHR) {
        s_wmux[i] = Wih[(size_t)i * 386 + 384];
        s_wmuy[i] = Wih[(size_t)i * 386 + 385];
        s_bhh[i]  = bhhg[i];
    }
    for (int i = tid; i < 512; i += NTHR) s_w5[i] = Wmu[i];
    for (int i = tid; i < 768; i += NTHR) s_w5[512 + i] = Wcov[i];
    if (tid < 64) { s_mux[tid] = 0.f; s_muy[tid] = 0.f; }

    // ================= PRECOMPUTE: h0 (buf 0, transposed) and gi_base (global) ==========
    {
        const int tx4 = tid & 15, ty4 = tid >> 4;
        const int j04 = tx4 * 4, m04 = ty4 * 2;
        float* s_zhT = s_w;          // [64 k][68]
        float* s_wtp = s_w + 4352;   // [64 k][68]   (fits in 15360-float W region)

        for (int jb = 0; jb < 16; ++jb) {
            ull acc[2][2];
            acc[0][0]=0ull; acc[0][1]=0ull; acc[1][0]=0ull; acc[1][1]=0ull;

            for (int kc = 0; kc < 6; ++kc) {
                __syncthreads();
                #pragma unroll
                for (int it = 0; it < 8; ++it) {
                    int idx = it * NTHR + tid;
                    int kk = idx & 63, rr = idx >> 6;
                    s_zhT[kk * 68 + rr] = zh[(size_t)(b0 + rr) * INDIM + kc * 64 + kk];
                    int jp = jb * 64 + rr;
                    const float* wrow = (jp < 256) ? (Wh0 + (size_t)jp * 384)
                                                   : (Wih + (size_t)(jp - 256) * 386);
                    s_wtp[kk * 68 + rr] = wrow[kc * 64 + kk];
                }
                __syncthreads();
                #pragma unroll 8
                for (int k = 0; k < 64; ++k) {
                    float2 hv = *(const float2*)&s_zhT[k * 68 + m04];
                    ull w0 = *(const ull*)&s_wtp[k * 68 + j04];
                    ull w1 = *(const ull*)&s_wtp[k * 68 + j04 + 2];
                    ull a0 = pack2(hv.x, hv.x), a1 = pack2(hv.y, hv.y);
                    ffma2(acc[0][0], a0, w0); ffma2(acc[0][1], a0, w1);
                    ffma2(acc[1][0], a1, w0); ffma2(acc[1][1], a1, w1);
                }
            }
            float v[2][4];
            #pragma unroll
            for (int m = 0; m < 2; ++m) {
                unpack2(acc[m][0], v[m][0], v[m][1]);
                unpack2(acc[m][1], v[m][2], v[m][3]);
            }
            if (jb < 4) {
                #pragma unroll
                for (int jj = 0; jj < 4; ++jj) {
                    int j = jb * 64 + j04 + jj;
                    float b = bh0[j];
                    *(float2*)&sm[OFF_HT + (size_t)j * HT_STRIDE + m04] =
                        make_float2(v[0][jj] + b, v[1][jj] + b);
                }
            } else {
                int gcol = jb * 64 - 256 + j04;
                float4 bb = *(const float4*)&bih[gcol];
                #pragma unroll
                for (int m = 0; m < 2; ++m) {
                    *(float4*)&g_gi[(size_t)(b0 + m04 + m) * 768 + gcol] =
                        make_float4(v[m][0] + bb.x, v[m][1] + bb.y, v[m][2] + bb.z, v[m][3] + bb.w);
                }
            }
        }
        __syncthreads();    // precompute fully done before W staging reuses s_w
    }

    const size_t covbase = (size_t)B * HORIZON * 2;

    // Prime the per-warp W pipeline
    issue_chunk_w(s_w_u32, Whh, 0, warp, lane);
    CPA_COMMIT();

    // ================= 30-step GRU recurrence (no per-kc block barriers) =================
    int cur = 0;
    #pragma unroll 1
    for (int t = 0; t < HORIZON; ++t) {
        float* hcur = sm + OFF_HT + cur * HT_SIZE;
        float* hnxt = sm + OFF_HT + (1 - cur) * HT_SIZE;

        #pragma unroll 1
        for (int jb = 0; jb < 2; ++jb) {
            const int jg0 = jb * 128 + warp * 8 + jj0;   // this lane's two j: jg0, jg0+1

            // acc[gate][j2][mpair], seeded with b_hh (duplicated into both halves)
            ull acc[3][2][4];
            #pragma unroll
            for (int g = 0; g < 3; ++g)
                #pragma unroll
                for (int j2 = 0; j2 < 2; ++j2) {
                    float b = s_bhh[g * 256 + jg0 + j2];
                    ull bb = pack2(b, b);
                    #pragma unroll
                    for (int mp = 0; mp < 4; ++mp) acc[g][j2][mp] = bb;
                }

            #pragma unroll 1
            for (int kc = 0; kc < 16; ++kc) {
                const int c = jb * 16 + kc;
                issue_chunk_w(s_w_u32, Whh, (c + 1) & 31, warp, lane);
                CPA_COMMIT();
                CPA_WAIT1();   // warp-local: chunk c landed in this warp's buffer

                const float* wb  = s_w + (warp * 2 + (c & 1)) * WARP_WBUF;
                const float* hch = hcur + (size_t)(kc * 16) * HT_STRIDE + m0;

                #pragma unroll
                for (int kg = 0; kg < 4; ++kg) {
                    float4 w4[3][2];
                    #pragma unroll
                    for (int g = 0; g < 3; ++g)
                        #pragma unroll
                        for (int j2 = 0; j2 < 2; ++j2)
                            w4[g][j2] = *(const float4*)&wb[(g * 8 + jj0 + j2) * W_ROWPAD + kg * 4];
                    #pragma unroll
                    for (int kk = 0; kk < 4; ++kk) {
                        const float* hr = hch + (size_t)(kg * 4 + kk) * HT_STRIDE;
                        ulonglong2 q0 = *(const ulonglong2*)hr;        // m pairs 0..1
                        ulonglong2 q1 = *(const ulonglong2*)(hr + 4);  // m pairs 2..3
                        #pragma unroll
                        for (int g = 0; g < 3; ++g)
                            #pragma unroll
                            for (int j2 = 0; j2 < 2; ++j2) {
                                float ws = ((const float*)&w4[g][j2])[kk];
                                ull d = pack2(ws, ws);
                                ffma2(acc[g][j2][0], q0.x, d);
                                ffma2(acc[g][j2][1], q0.y, d);
                                ffma2(acc[g][j2][2], q1.x, d);
                                ffma2(acc[g][j2][3], q1.y, d);
                            }
                    }
                }
                // no barrier: buffer (c&1) is private to this warp and fully consumed
                // before chunk c+2 (which overwrites it) is issued next iteration.
            }

            // ---- gate epilogue: 2 j x 8 m GRU cells ----
            #pragma unroll
            for (int j2 = 0; j2 < 2; ++j2) {
                const int j = jg0 + j2;
                float fr[8], fz[8], fn[8];
                #pragma unroll
                for (int mp = 0; mp < 4; ++mp) {
                    unpack2(acc[0][j2][mp], fr[2*mp], fr[2*mp+1]);
                    unpack2(acc[1][j2][mp], fz[2*mp], fz[2*mp+1]);
                    unpack2(acc[2][j2][mp], fn[2*mp], fn[2*mp+1]);
                }
                float wxr = s_wmux[j], wxz = s_wmux[256 + j], wxn = s_wmux[512 + j];
                float wyr = s_wmuy[j], wyz = s_wmuy[256 + j], wyn = s_wmuy[512 + j];

                const float* hp = &hcur[(size_t)j * HT_STRIDE + m0];
                float4 o0 = *(const float4*)hp;
                float4 o1 = *(const float4*)(hp + 4);
                float ho[8] = {o0.x,o0.y,o0.z,o0.w,o1.x,o1.y,o1.z,o1.w};

                float hnew[8];
                #pragma unroll
                for (int m = 0; m < 8; ++m) {
                    const float* gp = &g_gi[(size_t)(b0 + m0 + m) * 768 + j];
                    float gr = gp[0], gz = gp[256], gn = gp[512];
                    float mx = s_mux[m0 + m], my = s_muy[m0 + m];
                    float r  = sigf(gr + mx * wxr + my * wyr + fr[m]);
                    float z  = sigf(gz + mx * wxz + my * wyz + fz[m]);
                    float n  = tanh_fast(gn + mx * wxn + my * wyn + r * fn[m]);
                    hnew[m] = (1.f - z) * n + z * ho[m];
                }
                float* hq = &hnxt[(size_t)j * HT_STRIDE + m0];
                *(float4*)hq       = make_float4(hnew[0], hnew[1], hnew[2], hnew[3]);
                *(float4*)(hq + 4) = make_float4(hnew[4], hnew[5], hnew[6], hnew[7]);
            }
        } // jb

        __syncthreads();   // hnxt complete, publish for mu/cov + next step

        // ---- mu / cov: 5 dots of length 256 per batch row (320 tasks) ----
        if (tid < 320) {
            int o = tid >> 6; int m = tid & 63;
            const float* wrow = &s_w5[o * 256];
            const float* hc = hnxt + m;
            float a0 = 0.f, a1 = 0.f, a2 = 0.f, a3 = 0.f;
            #pragma unroll 4
            for (int k = 0; k < 256; k += 4) {
                a0 += hc[(size_t)(k    ) * HT_STRIDE] * wrow[k    ];
                a1 += hc[(size_t)(k + 1) * HT_STRIDE] * wrow[k + 1];
                a2 += hc[(size_t)(k + 2) * HT_STRIDE] * wrow[k + 2];
                a3 += hc[(size_t)(k + 3) * HT_STRIDE] * wrow[k + 3];
            }
            float acc5 = (a0 + a1) + (a2 + a3);
            size_t idx2 = ((size_t)(b0 + m) * HORIZON + t);
            if (o == 0) {
                float vv = acc5 + bmu[0]; out[idx2 * 2]     = vv; s_mux[m] = vv;
            } else if (o == 1) {
                float vv = acc5 + bmu[1]; out[idx2 * 2 + 1] = vv; s_muy[m] = vv;
            } else if (o == 2) {
                float vv = fminf(fmaxf(acc5 + bcov[0], 0.2f), 1.0f);
                out[covbase + idx2 * 4]     = vv;
            } else if (o == 3) {
                float vv = fminf(fmaxf(acc5 + bcov[1], -0.1f), 0.1f);
                out[covbase + idx2 * 4 + 1] = vv;
                out[covbase + idx2 * 4 + 2] = vv;
            } else {
                float vv = fminf(fmaxf(acc5 + bcov[2], 0.2f), 1.0f);
                out[covbase + idx2 * 4 + 3] = vv;
            }
        }
        __syncthreads();   // s_mux/s_muy published before next step's epilogue reads
        cur ^= 1;
    }

    CPA_WAIT0();   // drain final speculative prefetch
}

extern "C" void kernel_launch(void* const* d_in, const int* in_sizes, int n_in,
                              void* d_out, int out_size) {
    const float* zh   = (const float*)d_in[0];
    const float* Wh0  = (const float*)d_in[1];
    const float* bh0  = (const float*)d_in[2];
    const float* Wih  = (const float*)d_in[3];
    const float* bih  = (const float*)d_in[4];
    const float* Whh  = (const float*)d_in[5];
    const float* bhh  = (const float*)d_in[6];
    const float* Wmu  = (const float*)d_in[7];
    const float* bmu  = (const float*)d_in[8];
    const float* Wcov = (const float*)d_in[9];
    const float* bcov = (const float*)d_in[10];
    float* out = (float*)d_out;

    int B = in_sizes[0] / INDIM;
    cudaFuncSetAttribute(gru_decoder_kernel,
                         cudaFuncAttributeMaxDynamicSharedMemorySize, SMEM_FLOATS * 4);
    gru_decoder_kernel<<<B / 64, NTHR, SMEM_FLOATS * 4>>>(
        zh, Wh0, bh0, Wih, bih, Whh, bhh, Wmu, bmu, Wcov, bcov, out, B);
}

// round 7
// speedup vs baseline: 1.2526x; 1.2526x over previous
#include <cuda_runtime.h>
#include <cstdint>

#define HORIZON 30
#define INDIM   384
#define BMAX    65536

typedef unsigned long long ull;

// gi_base scratch: [B, 768] fp32 (192 MB) static device scratch.
__device__ float g_gi[(size_t)BMAX * 768];

__device__ __forceinline__ ull pack2(float lo, float hi) {
    ull r; asm("mov.b64 %0, {%1, %2};" : "=l"(r) : "f"(lo), "f"(hi)); return r;
}
__device__ __forceinline__ void ffma2(ull& d, ull a, ull b) {
    asm("fma.rn.f32x2 %0, %1, %2, %0;" : "+l"(d) : "l"(a), "l"(b));
}
__device__ __forceinline__ void unpack2(ull v, float& lo, float& hi) {
    asm("mov.b64 {%0, %1}, %2;" : "=f"(lo), "=f"(hi) : "l"(v));
}
__device__ __forceinline__ float sigf(float x) {
    return __fdividef(1.f, 1.f + __expf(-x));
}
__device__ __forceinline__ float tanh_fast(float x) {
    float t = __expf(2.f * x);
    return 1.f - __fdividef(2.f, t + 1.f);
}
__device__ __forceinline__ void cpa16(uint32_t s, const void* g) {
    asm volatile("cp.async.cg.shared.global [%0], [%1], 16;" :: "r"(s), "l"(g));
}
#define CPA_COMMIT() asm volatile("cp.async.commit_group;")
#define CPA_WAIT1()  asm volatile("cp.async.wait_group 1;")
#define CPA_WAIT0()  asm volatile("cp.async.wait_group 0;")

// ---------------- shared memory layout (floats) ----------------
// h rows: 64 floats of data with a 4-float gap after m=31 (bank de-conflict),
// stride 72. Data at [0..31] and [36..67].
#define HT_STRIDE 72
#define HT_SIZE   (256 * HT_STRIDE)          // 18432
#define OFF_HT    0                           // 2 ping-pong buffers
#define OFF_W     (2 * HT_SIZE)              // 36864
#define W_ROWPAD  20                          // 16 k + 4 pad
#define WARP_WBUF (24 * W_ROWPAD)            // 480 floats: 24 rows x 16 k
#define W_REGION  (16 * 2 * WARP_WBUF)       // 15360 floats
#define OFF_WMUX  (OFF_W + W_REGION)         // 52224
#define OFF_WMUY  (OFF_WMUX + 768)
#define OFF_BHH   (OFF_WMUY + 768)
#define OFF_W5    (OFF_BHH + 768)
#define OFF_MUX   (OFF_W5 + 1280)
#define OFF_MUY   (OFF_MUX + 64)
#define SMEM_FLOATS (OFF_MUY + 64)           // 55936 floats = 223744 B (< 227 KB)

#define NTHR 512

__device__ __forceinline__ int mgap(int m) { return m + ((m >> 5) << 2); }  // +4 if m>=32

// Per-warp private W staging: warp owns hidden slice j in [jb*128 + warp*8, +8)
// for all 3 gates -> 24 Whh rows. Chunk c = jb*16 + kc covers k in [kc*16, +16).
__device__ __forceinline__ void issue_chunk_w(uint32_t s_w_u32, const float* __restrict__ Whh,
                                              int c, int warp, int lane) {
    const int jb = (c >> 4) & 1;
    const int kc = c & 15;
    const uint32_t sbuf = s_w_u32 + (uint32_t)((warp * 2 + (c & 1)) * WARP_WBUF * 4);
    #pragma unroll
    for (int o = 0; o < 3; ++o) {
        int t = o * 32 + lane;            // 96 tasks: 24 rows x 4 quads
        int r = t >> 2, q = t & 3;
        int g = r >> 3, jj = r & 7;
        const float* gp = Whh + (size_t)(g * 256 + jb * 128 + warp * 8 + jj) * 256
                              + kc * 16 + q * 4;
        cpa16(sbuf + (uint32_t)((r * W_ROWPAD + q * 4) * 4), gp);
    }
}

__global__ void __launch_bounds__(NTHR, 1)
gru_decoder_kernel(const float* __restrict__ zh,  const float* __restrict__ Wh0,
                   const float* __restrict__ bh0, const float* __restrict__ Wih,
                   const float* __restrict__ bih, const float* __restrict__ Whh,
                   const float* __restrict__ bhhg,const float* __restrict__ Wmu,
                   const float* __restrict__ bmu, const float* __restrict__ Wcov,
                   const float* __restrict__ bcov,float* __restrict__ out, int B)
{
    extern __shared__ float sm[];
    float* s_w    = sm + OFF_W;
    float* s_wmux = sm + OFF_WMUX;
    float* s_wmuy = sm + OFF_WMUY;
    float* s_bhh  = sm + OFF_BHH;
    float* s_w5   = sm + OFF_W5;
    float* s_mux  = sm + OFF_MUX;
    float* s_muy  = sm + OFF_MUY;

    const int tid  = threadIdx.x;
    const int warp = tid >> 5, lane = tid & 31;
    const int m0   = (lane & 7) * 8;          // 8 batch rows (4 f32x2 pairs)
    const int m0p  = mgap(m0);                // gapped offset into h rows
    const int jj0  = (lane >> 3) * 2;         // 2 adjacent j within warp's 8-j slice
    const int b0   = blockIdx.x * 64;

    const uint32_t s_w_u32 = (uint32_t)__cvta_generic_to_shared(s_w);

    // ---- one-time small-weight staging ----
    for (int i = tid; i < 768; i += NTHR) {
        s_wmux[i] = Wih[(size_t)i * 386 + 384];
        s_wmuy[i] = Wih[(size_t)i * 386 + 385];
        s_bhh[i]  = bhhg[i];
    }
    for (int i = tid; i < 512; i += NTHR) s_w5[i] = Wmu[i];
    for (int i = tid; i < 768; i += NTHR) s_w5[512 + i] = Wcov[i];
    if (tid < 64) { s_mux[tid] = 0.f; s_muy[tid] = 0.f; }

    // ================= PRECOMPUTE: h0 (buf 0, gapped transposed) and gi_base ==========
    {
        const int tx4 = tid & 15, ty4 = tid >> 4;
        const int j04 = tx4 * 4, m04 = ty4 * 2;
        const int m04p = mgap(m04);
        float* s_zhT = s_w;          // [64 k][68]
        float* s_wtp = s_w + 4352;   // [64 k][68]   (8704 <= 15360 region)

        for (int jb = 0; jb < 16; ++jb) {
            ull acc[2][2];
            acc[0][0]=0ull; acc[0][1]=0ull; acc[1][0]=0ull; acc[1][1]=0ull;

            for (int kc = 0; kc < 6; ++kc) {
                __syncthreads();
                #pragma unroll
                for (int it = 0; it < 8; ++it) {
                    int idx = it * NTHR + tid;
                    int kk = idx & 63, rr = idx >> 6;
                    s_zhT[kk * 68 + rr] = zh[(size_t)(b0 + rr) * INDIM + kc * 64 + kk];
                    int jp = jb * 64 + rr;
                    const float* wrow = (jp < 256) ? (Wh0 + (size_t)jp * 384)
                                                   : (Wih + (size_t)(jp - 256) * 386);
                    s_wtp[kk * 68 + rr] = wrow[kc * 64 + kk];
                }
                __syncthreads();
                #pragma unroll 8
                for (int k = 0; k < 64; ++k) {
                    float2 hv = *(const float2*)&s_zhT[k * 68 + m04];
                    ull w0 = *(const ull*)&s_wtp[k * 68 + j04];
                    ull w1 = *(const ull*)&s_wtp[k * 68 + j04 + 2];
                    ull a0 = pack2(hv.x, hv.x), a1 = pack2(hv.y, hv.y);
                    ffma2(acc[0][0], a0, w0); ffma2(acc[0][1], a0, w1);
                    ffma2(acc[1][0], a1, w0); ffma2(acc[1][1], a1, w1);
                }
            }
            float v[2][4];
            #pragma unroll
            for (int m = 0; m < 2; ++m) {
                unpack2(acc[m][0], v[m][0], v[m][1]);
                unpack2(acc[m][1], v[m][2], v[m][3]);
            }
            if (jb < 4) {
                #pragma unroll
                for (int jj = 0; jj < 4; ++jj) {
                    int j = jb * 64 + j04 + jj;
                    float b = bh0[j];
                    *(float2*)&sm[OFF_HT + (size_t)j * HT_STRIDE + m04p] =
                        make_float2(v[0][jj] + b, v[1][jj] + b);
                }
            } else {
                int gcol = jb * 64 - 256 + j04;
                float4 bb = *(const float4*)&bih[gcol];
                #pragma unroll
                for (int m = 0; m < 2; ++m) {
                    *(float4*)&g_gi[(size_t)(b0 + m04 + m) * 768 + gcol] =
                        make_float4(v[m][0] + bb.x, v[m][1] + bb.y, v[m][2] + bb.z, v[m][3] + bb.w);
                }
            }
        }
        __syncthreads();    // precompute done before W staging reuses s_w
    }

    const size_t covbase = (size_t)B * HORIZON * 2;

    // Prime per-warp W pipeline, depth 2 (chunks 0 and 1)
    issue_chunk_w(s_w_u32, Whh, 0, warp, lane);
    CPA_COMMIT();
    issue_chunk_w(s_w_u32, Whh, 1, warp, lane);
    CPA_COMMIT();

    // ================= 30-step GRU recurrence (no per-kc block barriers) =================
    int cur = 0;
    #pragma unroll 1
    for (int t = 0; t < HORIZON; ++t) {
        float* hcur = sm + OFF_HT + cur * HT_SIZE;
        float* hnxt = sm + OFF_HT + (1 - cur) * HT_SIZE;

        #pragma unroll 1
        for (int jb = 0; jb < 2; ++jb) {
            const int jg0 = jb * 128 + warp * 8 + jj0;   // lane's j-pair: jg0, jg0+1

            ull acc[3][2][4];
            #pragma unroll
            for (int g = 0; g < 3; ++g)
                #pragma unroll
                for (int j2 = 0; j2 < 2; ++j2) {
                    float b = s_bhh[g * 256 + jg0 + j2];
                    ull bb = pack2(b, b);
                    #pragma unroll
                    for (int mp = 0; mp < 4; ++mp) acc[g][j2][mp] = bb;
                }

            #pragma unroll 1
            for (int kc = 0; kc < 16; ++kc) {
                const int c = jb * 16 + kc;
                CPA_WAIT1();   // chunk c resident in this warp's buffer (c&1)

                const float* wb  = s_w + (warp * 2 + (c & 1)) * WARP_WBUF;
                const float* hch = hcur + (size_t)(kc * 16) * HT_STRIDE + m0p;

                #pragma unroll
                for (int kg = 0; kg < 4; ++kg) {
                    float4 w4[3][2];
                    #pragma unroll
                    for (int g = 0; g < 3; ++g)
                        #pragma unroll
                        for (int j2 = 0; j2 < 2; ++j2)
                            w4[g][j2] = *(const float4*)&wb[(g * 8 + jj0 + j2) * W_ROWPAD + kg * 4];
                    #pragma unroll
                    for (int kk = 0; kk < 4; ++kk) {
                        const float* hr = hch + (size_t)(kg * 4 + kk) * HT_STRIDE;
                        ulonglong2 q0 = *(const ulonglong2*)hr;        // m pairs 0..1 (CF)
                        ulonglong2 q1 = *(const ulonglong2*)(hr + 4);  // m pairs 2..3 (CF)
                        #pragma unroll
                        for (int g = 0; g < 3; ++g)
                            #pragma unroll
                            for (int j2 = 0; j2 < 2; ++j2) {
                                float ws = ((const float*)&w4[g][j2])[kk];
                                ull d = pack2(ws, ws);
                                ffma2(acc[g][j2][0], q0.x, d);
                                ffma2(acc[g][j2][1], q0.y, d);
                                ffma2(acc[g][j2][2], q1.x, d);
                                ffma2(acc[g][j2][3], q1.y, d);
                            }
                    }
                }
                // Issue chunk c+2 into buf (c&1) AFTER the FFMA2s above have issued.
                // In-order issue + scoreboard (FFMA2 waits on the w4/h LDS) guarantees
                // the buffer reads completed before this overwrite can land.
                issue_chunk_w(s_w_u32, Whh, (c + 2) & 31, warp, lane);
                CPA_COMMIT();
            }

            // ---- gate epilogue: j-pair x 8 m GRU cells ----
            float fr[2][8], fz[2][8], fn[2][8];
            #pragma unroll
            for (int j2 = 0; j2 < 2; ++j2)
                #pragma unroll
                for (int mp = 0; mp < 4; ++mp) {
                    unpack2(acc[0][j2][mp], fr[j2][2*mp], fr[j2][2*mp+1]);
                    unpack2(acc[1][j2][mp], fz[j2][2*mp], fz[j2][2*mp+1]);
                    unpack2(acc[2][j2][mp], fn[j2][2*mp], fn[j2][2*mp+1]);
                }

            float2 wxr = *(const float2*)&s_wmux[jg0];
            float2 wxz = *(const float2*)&s_wmux[256 + jg0];
            float2 wxn = *(const float2*)&s_wmux[512 + jg0];
            float2 wyr = *(const float2*)&s_wmuy[jg0];
            float2 wyz = *(const float2*)&s_wmuy[256 + jg0];
            float2 wyn = *(const float2*)&s_wmuy[512 + jg0];

            float ho[2][8], hnew[2][8];
            #pragma unroll
            for (int j2 = 0; j2 < 2; ++j2) {
                const float* hp = &hcur[(size_t)(jg0 + j2) * HT_STRIDE + m0p];
                float4 o0 = *(const float4*)hp;
                float4 o1 = *(const float4*)(hp + 4);
                ho[j2][0]=o0.x; ho[j2][1]=o0.y; ho[j2][2]=o0.z; ho[j2][3]=o0.w;
                ho[j2][4]=o1.x; ho[j2][5]=o1.y; ho[j2][6]=o1.z; ho[j2][7]=o1.w;
            }

            #pragma unroll
            for (int m = 0; m < 8; ++m) {
                const float* gp = &g_gi[(size_t)(b0 + m0 + m) * 768 + jg0];
                float2 gr = *(const float2*)gp;
                float2 gz = *(const float2*)(gp + 256);
                float2 gn = *(const float2*)(gp + 512);
                float mx = s_mux[m0 + m], my = s_muy[m0 + m];
                {
                    float r  = sigf(gr.x + mx * wxr.x + my * wyr.x + fr[0][m]);
                    float z  = sigf(gz.x + mx * wxz.x + my * wyz.x + fz[0][m]);
                    float n  = tanh_fast(gn.x + mx * wxn.x + my * wyn.x + r * fn[0][m]);
                    hnew[0][m] = (1.f - z) * n + z * ho[0][m];
                }
                {
                    float r  = sigf(gr.y + mx * wxr.y + my * wyr.y + fr[1][m]);
                    float z  = sigf(gz.y + mx * wxz.y + my * wyz.y + fz[1][m]);
                    float n  = tanh_fast(gn.y + mx * wxn.y + my * wyn.y + r * fn[1][m]);
                    hnew[1][m] = (1.f - z) * n + z * ho[1][m];
                }
            }
            #pragma unroll
            for (int j2 = 0; j2 < 2; ++j2) {
                float* hq = &hnxt[(size_t)(jg0 + j2) * HT_STRIDE + m0p];
                *(float4*)hq       = make_float4(hnew[j2][0], hnew[j2][1], hnew[j2][2], hnew[j2][3]);
                *(float4*)(hq + 4) = make_float4(hnew[j2][4], hnew[j2][5], hnew[j2][6], hnew[j2][7]);
            }
        } // jb

        __syncthreads();   // hnxt complete, publish for mu/cov + next step

        // ---- mu / cov: 5 dots of length 256 per batch row (320 tasks) ----
        if (tid < 320) {
            int o = tid >> 6; int m = tid & 63;
            const float* wrow = &s_w5[o * 256];
            const float* hc = hnxt + mgap(m);
            float a0 = 0.f, a1 = 0.f, a2 = 0.f, a3 = 0.f;
            #pragma unroll 4
            for (int k = 0; k < 256; k += 4) {
                a0 += hc[(size_t)(k    ) * HT_STRIDE] * wrow[k    ];
                a1 += hc[(size_t)(k + 1) * HT_STRIDE] * wrow[k + 1];
                a2 += hc[(size_t)(k + 2) * HT_STRIDE] * wrow[k + 2];
                a3 += hc[(size_t)(k + 3) * HT_STRIDE] * wrow[k + 3];
            }
            float acc5 = (a0 + a1) + (a2 + a3);
            size_t idx2 = ((size_t)(b0 + m) * HORIZON + t);
            if (o == 0) {
                float vv = acc5 + bmu[0]; out[idx2 * 2]     = vv; s_mux[m] = vv;
            } else if (o == 1) {
                float vv = acc5 + bmu[1]; out[idx2 * 2 + 1] = vv; s_muy[m] = vv;
            } else if (o == 2) {
                float vv = fminf(fmaxf(acc5 + bcov[0], 0.2f), 1.0f);
                out[covbase + idx2 * 4]     = vv;
            } else if (o == 3) {
                float vv = fminf(fmaxf(acc5 + bcov[1], -0.1f), 0.1f);
                out[covbase + idx2 * 4 + 1] = vv;
                out[covbase + idx2 * 4 + 2] = vv;
            } else {
                float vv = fminf(fmaxf(acc5 + bcov[2], 0.2f), 1.0f);
                out[covbase + idx2 * 4 + 3] = vv;
            }
        }
        __syncthreads();   // s_mux/s_muy published before next step reads
        cur ^= 1;
    }

    CPA_WAIT0();   // drain speculative prefetches
}

extern "C" void kernel_launch(void* const* d_in, const int* in_sizes, int n_in,
                              void* d_out, int out_size) {
    const float* zh   = (const float*)d_in[0];
    const float* Wh0  = (const float*)d_in[1];
    const float* bh0  = (const float*)d_in[2];
    const float* Wih  = (const float*)d_in[3];
    const float* bih  = (const float*)d_in[4];
    const float* Whh  = (const float*)d_in[5];
    const float* bhh  = (const float*)d_in[6];
    const float* Wmu  = (const float*)d_in[7];
    const float* bmu  = (const float*)d_in[8];
    const float* Wcov = (const float*)d_in[9];
    const float* bcov = (const float*)d_in[10];
    float* out = (float*)d_out;

    int B = in_sizes[0] / INDIM;
    cudaFuncSetAttribute(gru_decoder_kernel,
                         cudaFuncAttributeMaxDynamicSharedMemorySize, SMEM_FLOATS * 4);
    gru_decoder_kernel<<<B / 64, NTHR, SMEM_FLOATS * 4>>>(
        zh, Wh0, bh0, Wih, bih, Whh, bhh, Wmu, bmu, Wcov, bcov, out, B);
}

// round 8
// speedup vs baseline: 1.2853x; 1.0261x over previous
#include <cuda_runtime.h>
#include <cstdint>

#define HORIZON 30
#define INDIM   384
#define BMAX    65536

typedef unsigned long long ull;

// gi_base scratch, TRANSPOSED layout: [row = gate*256 + j][B] fp32 (192 MB).
__device__ float g_gi[(size_t)768 * BMAX];

__device__ __forceinline__ ull pack2(float lo, float hi) {
    ull r; asm("mov.b64 %0, {%1, %2};" : "=l"(r) : "f"(lo), "f"(hi)); return r;
}
__device__ __forceinline__ void ffma2(ull& d, ull a, ull b) {
    asm("fma.rn.f32x2 %0, %1, %2, %0;" : "+l"(d) : "l"(a), "l"(b));
}
__device__ __forceinline__ void unpack2(ull v, float& lo, float& hi) {
    asm("mov.b64 {%0, %1}, %2;" : "=f"(lo), "=f"(hi) : "l"(v));
}
__device__ __forceinline__ float sigf(float x) {
    return __fdividef(1.f, 1.f + __expf(-x));
}
__device__ __forceinline__ float tanh_fast(float x) {
    float t = __expf(2.f * x);
    return 1.f - __fdividef(2.f, t + 1.f);
}
__device__ __forceinline__ void cpa16(uint32_t s, const void* g) {
    asm volatile("cp.async.cg.shared.global [%0], [%1], 16;" :: "r"(s), "l"(g));
}
#define CPA_COMMIT() asm volatile("cp.async.commit_group;")
#define CPA_WAIT1()  asm volatile("cp.async.wait_group 1;")
#define CPA_WAIT0()  asm volatile("cp.async.wait_group 0;")

// ---------------- shared memory layout (floats) ----------------
#define HT_STRIDE 72
#define HT_SIZE   (256 * HT_STRIDE)          // 18432
#define OFF_HT    0                           // 2 ping-pong buffers
#define OFF_W     (2 * HT_SIZE)              // 36864
#define W_ROWPAD  20
#define WARP_WBUF (24 * W_ROWPAD)            // 480 floats
#define W_REGION  (16 * 2 * WARP_WBUF)       // 15360 floats
#define OFF_WMUX  (OFF_W + W_REGION)         // 52224
#define OFF_WMUY  (OFF_WMUX + 768)
#define OFF_BHH   (OFF_WMUY + 768)
#define OFF_W5    (OFF_BHH + 768)
#define OFF_MUX   (OFF_W5 + 1280)
#define OFF_MUY   (OFF_MUX + 64)
#define SMEM_FLOATS (OFF_MUY + 64)           // 55936 floats = 223744 B

#define NTHR 512

__device__ __forceinline__ int mgap(int m) { return m + ((m >> 5) << 2); }

// Per-warp private W staging (chunk c = jb*16 + kc; buffer index = c&1 = kc&1).
__device__ __forceinline__ void issue_chunk_w(uint32_t s_w_u32, const float* __restrict__ Whh,
                                              int c, int warp, int lane) {
    const int jb = (c >> 4) & 1;
    const int kc = c & 15;
    const uint32_t sbuf = s_w_u32 + (uint32_t)((warp * 2 + (c & 1)) * WARP_WBUF * 4);
    #pragma unroll
    for (int o = 0; o < 3; ++o) {
        int t = o * 32 + lane;            // 96 tasks: 24 rows x 4 quads
        int r = t >> 2, q = t & 3;
        int g = r >> 3, jj = r & 7;
        const float* gp = Whh + (size_t)(g * 256 + jb * 128 + warp * 8 + jj) * 256
                              + kc * 16 + q * 4;
        cpa16(sbuf + (uint32_t)((r * W_ROWPAD + q * 4) * 4), gp);
    }
}

__global__ void __launch_bounds__(NTHR, 1)
gru_decoder_kernel(const float* __restrict__ zh,  const float* __restrict__ Wh0,
                   const float* __restrict__ bh0, const float* __restrict__ Wih,
                   const float* __restrict__ bih, const float* __restrict__ Whh,
                   const float* __restrict__ bhhg,const float* __restrict__ Wmu,
                   const float* __restrict__ bmu, const float* __restrict__ Wcov,
                   const float* __restrict__ bcov,float* __restrict__ out, int B)
{
    extern __shared__ float sm[];
    float* s_w    = sm + OFF_W;
    float* s_wmux = sm + OFF_WMUX;
    float* s_wmuy = sm + OFF_WMUY;
    float* s_bhh  = sm + OFF_BHH;
    float* s_w5   = sm + OFF_W5;
    float* s_mux  = sm + OFF_MUX;
    float* s_muy  = sm + OFF_MUY;

    const int tid  = threadIdx.x;
    const int warp = tid >> 5, lane = tid & 31;
    const int wjb  = warp & 1;                // jb-stagger parity
    const int m0   = (lane & 7) * 8;
    const int m0p  = mgap(m0);
    const int jj0  = (lane >> 3) * 2;
    const int b0   = blockIdx.x * 64;
    const size_t Bs = (size_t)B;

    const uint32_t s_w_u32 = (uint32_t)__cvta_generic_to_shared(s_w);

    // ---- one-time small-weight staging ----
    for (int i = tid; i < 768; i += NTHR) {
        s_wmux[i] = Wih[(size_t)i * 386 + 384];
        s_wmuy[i] = Wih[(size_t)i * 386 + 385];
        s_bhh[i]  = bhhg[i];
    }
    for (int i = tid; i < 512; i += NTHR) s_w5[i] = Wmu[i];
    for (int i = tid; i < 768; i += NTHR) s_w5[512 + i] = Wcov[i];
    if (tid < 64) { s_mux[tid] = 0.f; s_muy[tid] = 0.f; }

    // ================= PRECOMPUTE: h0 (buf 0, gapped transposed) and gi_base ==========
    {
        const int tx4 = tid & 15, ty4 = tid >> 4;
        const int j04 = tx4 * 4, m04 = ty4 * 2;
        const int m04p = mgap(m04);
        float* s_zhT = s_w;          // [64 k][68]
        float* s_wtp = s_w + 4352;   // [64 k][68]

        for (int jb = 0; jb < 16; ++jb) {
            ull acc[2][2];
            acc[0][0]=0ull; acc[0][1]=0ull; acc[1][0]=0ull; acc[1][1]=0ull;

            for (int kc = 0; kc < 6; ++kc) {
                __syncthreads();
                #pragma unroll
                for (int it = 0; it < 8; ++it) {
                    int idx = it * NTHR + tid;
                    int kk = idx & 63, rr = idx >> 6;
                    s_zhT[kk * 68 + rr] = zh[(size_t)(b0 + rr) * INDIM + kc * 64 + kk];
                    int jp = jb * 64 + rr;
                    const float* wrow = (jp < 256) ? (Wh0 + (size_t)jp * 384)
                                                   : (Wih + (size_t)(jp - 256) * 386);
                    s_wtp[kk * 68 + rr] = wrow[kc * 64 + kk];
                }
                __syncthreads();
                #pragma unroll 8
                for (int k = 0; k < 64; ++k) {
                    float2 hv = *(const float2*)&s_zhT[k * 68 + m04];
                    ull w0 = *(const ull*)&s_wtp[k * 68 + j04];
                    ull w1 = *(const ull*)&s_wtp[k * 68 + j04 + 2];
                    ull a0 = pack2(hv.x, hv.x), a1 = pack2(hv.y, hv.y);
                    ffma2(acc[0][0], a0, w0); ffma2(acc[0][1], a0, w1);
                    ffma2(acc[1][0], a1, w0); ffma2(acc[1][1], a1, w1);
                }
            }
            float v[2][4];
            #pragma unroll
            for (int m = 0; m < 2; ++m) {
                unpack2(acc[m][0], v[m][0], v[m][1]);
                unpack2(acc[m][1], v[m][2], v[m][3]);
            }
            if (jb < 4) {
                #pragma unroll
                for (int jj = 0; jj < 4; ++jj) {
                    int j = jb * 64 + j04 + jj;
                    float b = bh0[j];
                    *(float2*)&sm[OFF_HT + (size_t)j * HT_STRIDE + m04p] =
                        make_float2(v[0][jj] + b, v[1][jj] + b);
                }
            } else {
                // TRANSPOSED gi store: row (gate*256+j) x [B]
                int gcol = jb * 64 - 256 + j04;
                float4 bb = *(const float4*)&bih[gcol];
                const float* bbp = (const float*)&bb;
                #pragma unroll
                for (int jj = 0; jj < 4; ++jj) {
                    *(float2*)&g_gi[(size_t)(gcol + jj) * Bs + b0 + m04] =
                        make_float2(v[0][jj] + bbp[jj], v[1][jj] + bbp[jj]);
                }
            }
        }
        __syncthreads();    // precompute done before W staging reuses s_w
    }

    const size_t covbase = (size_t)B * HORIZON * 2;

    // Prime per-warp W pipeline with this warp's first two chunks (its own jb order)
    issue_chunk_w(s_w_u32, Whh, wjb * 16 + 0, warp, lane);
    CPA_COMMIT();
    issue_chunk_w(s_w_u32, Whh, wjb * 16 + 1, warp, lane);
    CPA_COMMIT();

    // ================= 30-step GRU recurrence =================
    int cur = 0;
    #pragma unroll 1
    for (int t = 0; t < HORIZON; ++t) {
        float* hcur = sm + OFF_HT + cur * HT_SIZE;
        float* hnxt = sm + OFF_HT + (1 - cur) * HT_SIZE;

        #pragma unroll 1
        for (int jbi = 0; jbi < 2; ++jbi) {
            const int jb  = jbi ^ wjb;                    // staggered jb order per warp
            const int jg0 = jb * 128 + warp * 8 + jj0;    // lane's j-pair

            ull acc[3][2][4];
            #pragma unroll
            for (int g = 0; g < 3; ++g)
                #pragma unroll
                for (int j2 = 0; j2 < 2; ++j2) {
                    float b = s_bhh[g * 256 + jg0 + j2];
                    ull bb = pack2(b, b);
                    #pragma unroll
                    for (int mp = 0; mp < 4; ++mp) acc[g][j2][mp] = bb;
                }

            #pragma unroll 1
            for (int kc = 0; kc < 16; ++kc) {
                CPA_WAIT1();   // sequence element (jbi*16+kc) resident in buffer (kc&1)

                const float* wb  = s_w + (warp * 2 + (kc & 1)) * WARP_WBUF;
                const float* hch = hcur + (size_t)(kc * 16) * HT_STRIDE + m0p;

                #pragma unroll
                for (int kg = 0; kg < 4; ++kg) {
                    float4 w4[3][2];
                    #pragma unroll
                    for (int g = 0; g < 3; ++g)
                        #pragma unroll
                        for (int j2 = 0; j2 < 2; ++j2)
                            w4[g][j2] = *(const float4*)&wb[(g * 8 + jj0 + j2) * W_ROWPAD + kg * 4];
                    #pragma unroll
                    for (int kk = 0; kk < 4; ++kk) {
                        const float* hr = hch + (size_t)(kg * 4 + kk) * HT_STRIDE;
                        ulonglong2 q0 = *(const ulonglong2*)hr;
                        ulonglong2 q1 = *(const ulonglong2*)(hr + 4);
                        #pragma unroll
                        for (int g = 0; g < 3; ++g)
                            #pragma unroll
                            for (int j2 = 0; j2 < 2; ++j2) {
                                float ws = ((const float*)&w4[g][j2])[kk];
                                ull d = pack2(ws, ws);
                                ffma2(acc[g][j2][0], q0.x, d);
                                ffma2(acc[g][j2][1], q0.y, d);
                                ffma2(acc[g][j2][2], q1.x, d);
                                ffma2(acc[g][j2][3], q1.y, d);
                            }
                    }
                }
                // Issue sequence element s+2 (possibly wrapping into next step's order).
                {
                    int s2 = jbi * 16 + kc + 2;                 // up to 33
                    int jb2 = ((s2 >> 4) & 1) ^ wjb;
                    int c2  = jb2 * 16 + (s2 & 15);
                    issue_chunk_w(s_w_u32, Whh, c2, warp, lane);
                    CPA_COMMIT();
                }
            }

            // ---- gate epilogue: per j2 to bound register pressure ----
            #pragma unroll
            for (int j2 = 0; j2 < 2; ++j2) {
                const int j = jg0 + j2;
                float fr[8], fz[8], fn[8];
                #pragma unroll
                for (int mp = 0; mp < 4; ++mp) {
                    unpack2(acc[0][j2][mp], fr[2*mp], fr[2*mp+1]);
                    unpack2(acc[1][j2][mp], fz[2*mp], fz[2*mp+1]);
                    unpack2(acc[2][j2][mp], fn[2*mp], fn[2*mp+1]);
                }
                // coalesced gi loads (transposed layout): 8 m-consecutive floats per gate
                const float* pr = g_gi + (size_t)(        j) * Bs + b0 + m0;
                const float* pz = g_gi + (size_t)(256 +   j) * Bs + b0 + m0;
                const float* pn = g_gi + (size_t)(512 +   j) * Bs + b0 + m0;
                float4 gr0 = *(const float4*)pr,       gr1 = *(const float4*)(pr + 4);
                float4 gz0 = *(const float4*)pz,       gz1 = *(const float4*)(pz + 4);
                float4 gn0 = *(const float4*)pn,       gn1 = *(const float4*)(pn + 4);
                float gR[8] = {gr0.x,gr0.y,gr0.z,gr0.w, gr1.x,gr1.y,gr1.z,gr1.w};
                float gZ[8] = {gz0.x,gz0.y,gz0.z,gz0.w, gz1.x,gz1.y,gz1.z,gz1.w};
                float gN[8] = {gn0.x,gn0.y,gn0.z,gn0.w, gn1.x,gn1.y,gn1.z,gn1.w};

                float wxr = s_wmux[j], wxz = s_wmux[256 + j], wxn = s_wmux[512 + j];
                float wyr = s_wmuy[j], wyz = s_wmuy[256 + j], wyn = s_wmuy[512 + j];

                const float* hp = &hcur[(size_t)j * HT_STRIDE + m0p];
                float4 o0 = *(const float4*)hp;
                float4 o1 = *(const float4*)(hp + 4);
                float ho[8] = {o0.x,o0.y,o0.z,o0.w,o1.x,o1.y,o1.z,o1.w};

                float hnew[8];
                #pragma unroll
                for (int m = 0; m < 8; ++m) {
                    float mx = s_mux[m0 + m], my = s_muy[m0 + m];
                    float r  = sigf(gR[m] + mx * wxr + my * wyr + fr[m]);
                    float z  = sigf(gZ[m] + mx * wxz + my * wyz + fz[m]);
                    float n  = tanh_fast(gN[m] + mx * wxn + my * wyn + r * fn[m]);
                    hnew[m] = (1.f - z) * n + z * ho[m];
                }
                float* hq = &hnxt[(size_t)j * HT_STRIDE + m0p];
                *(float4*)hq       = make_float4(hnew[0], hnew[1], hnew[2], hnew[3]);
                *(float4*)(hq + 4) = make_float4(hnew[4], hnew[5], hnew[6], hnew[7]);
            }
        } // jbi

        __syncthreads();   // hnxt complete (both jb halves, all warps)

        // ---- mu / cov: 5 dots of length 256 per batch row (320 tasks) ----
        if (tid < 320) {
            int o = tid >> 6; int m = tid & 63;
            const float* wrow = &s_w5[o * 256];
            const float* hc = hnxt + mgap(m);
            float a0 = 0.f, a1 = 0.f, a2 = 0.f, a3 = 0.f;
            #pragma unroll 4
            for (int k = 0; k < 256; k += 4) {
                a0 += hc[(size_t)(k    ) * HT_STRIDE] * wrow[k    ];
                a1 += hc[(size_t)(k + 1) * HT_STRIDE] * wrow[k + 1];
                a2 += hc[(size_t)(k + 2) * HT_STRIDE] * wrow[k + 2];
                a3 += hc[(size_t)(k + 3) * HT_STRIDE] * wrow[k + 3];
            }
            float acc5 = (a0 + a1) + (a2 + a3);
            size_t idx2 = ((size_t)(b0 + m) * HORIZON + t);
            if (o == 0) {
                float vv = acc5 + bmu[0]; out[idx2 * 2]     = vv; s_mux[m] = vv;
            } else if (o == 1) {
                float vv = acc5 + bmu[1]; out[idx2 * 2 + 1] = vv; s_muy[m] = vv;
            } else if (o == 2) {
                float vv = fminf(fmaxf(acc5 + bcov[0], 0.2f), 1.0f);
                out[covbase + idx2 * 4]     = vv;
            } else if (o == 3) {
                float vv = fminf(fmaxf(acc5 + bcov[1], -0.1f), 0.1f);
                out[covbase + idx2 * 4 + 1] = vv;
                out[covbase + idx2 * 4 + 2] = vv;
            } else {
                float vv = fminf(fmaxf(acc5 + bcov[2], 0.2f), 1.0f);
                out[covbase + idx2 * 4 + 3] = vv;
            }
        }
        __syncthreads();   // s_mux/s_muy published before next step's epilogues read
        cur ^= 1;
    }

    CPA_WAIT0();   // drain speculative prefetches
}

extern "C" void kernel_launch(void* const* d_in, const int* in_sizes, int n_in,
                              void* d_out, int out_size) {
    const float* zh   = (const float*)d_in[0];
    const float* Wh0  = (const float*)d_in[1];
    const float* bh0  = (const float*)d_in[2];
    const float* Wih  = (const float*)d_in[3];
    const float* bih  = (const float*)d_in[4];
    const float* Whh  = (const float*)d_in[5];
    const float* bhh  = (const float*)d_in[6];
    const float* Wmu  = (const float*)d_in[7];
    const float* bmu  = (const float*)d_in[8];
    const float* Wcov = (const float*)d_in[9];
    const float* bcov = (const float*)d_in[10];
    float* out = (float*)d_out;

    int B = in_sizes[0] / INDIM;
    cudaFuncSetAttribute(gru_decoder_kernel,
                         cudaFuncAttributeMaxDynamicSharedMemorySize, SMEM_FLOATS * 4);
    gru_decoder_kernel<<<B / 64, NTHR, SMEM_FLOATS * 4>>>(
        zh, Wh0, bh0, Wih, bih, Whh, bhh, Wmu, bmu, Wcov, bcov, out, B);
}